// round 9
// baseline (speedup 1.0000x reference)
#include <cuda_runtime.h>

// SegmentPhysicsModel — FINAL (convergence re-verification of R5, the best
// jointly observed point: wall 6.624us, ncu 5.15us, rel_err 1.2e-7).
//
// Session findings baked in:
//  * 6 reference Newton solves -> 3 sign-selected solves (dark panel's root
//    is negative, clamps to 0).
//  * 25 Newton iters -> 2 damped division-free fixed-point steps (contraction
//    <= 3e-4/step; f32-converged in 2). 1-step works (3e-6) but 2-step is the
//    measured-best tick and keeps 25x margin.
//  * Raw rcp.approx / ex2.approx with prefolded log2e; expm1(Voc/vt_ref)
//    folded to a compile-time ex2 constant.
//  * Direct stride-11 loads of the 8 used features (year/month/day unused).
//    smem staging, warp staging, pair-vectorization all measured <= noise.
//  * TPB 256 / grid 512: fewer-larger CTAs beat finer grids (R6) and
//    2-sample threads (R8). Kernel is latency/launch-overhead bound; all
//    pipes < 15%.

#define TPB        256
#define NFEAT      11

#define JSC        170.0
#define ALPHA_ISC  0.0006f
#define T_REFC     298.15f
#define RS         0.01f
#define INV_RSH    0.002f
#define INV_GREF   (1.0f/1366.0f)
#define SOLAR_C    1366.0f
#define SUN_DIST   149600000.0f
#define NKB        (2.5f * 8.617333262e-05f)
#define LOG2E      1.4426950408889634

#define VT_REF_D   (2.5 * 8.617333262e-05 * 298.15)
#define INV_EM1_ARG ((float)(-(2.35 / VT_REF_D) * LOG2E))

#define C_A1       ((float)(JSC * 0.0604 * 0.0398))
#define C_A2       ((float)(JSC * 0.0403 * 0.0306))

#define STEP       0.99984f
#define NITER      2

__device__ __forceinline__ float ex2f(float z) {
    float r;
    asm("ex2.approx.f32 %0, %1;" : "=f"(r) : "f"(z));
    return r;
}

__device__ __forceinline__ float rcpf(float a) {
    float r;
    asm("rcp.approx.f32 %0, %1;" : "=f"(r) : "f"(a));
    return r;
}

__device__ __forceinline__ void fp_step(float& I, float v_cell, float c0,
                                        float i0, float k) {
    float u = fmaf(I, RS, v_cell);
    float e = ex2f(u * k);
    float t = fmaf(-i0, e, c0);
    t = fmaf(-INV_RSH, u, t);
    I = fmaf(STEP, t - I, I);
}

__global__ void __launch_bounds__(TPB)
segment_physics_kernel(const float* __restrict__ x,
                       const float* __restrict__ f_xn,
                       const float* __restrict__ f_yn,
                       const float* __restrict__ f_xp,
                       const float* __restrict__ f_yp,
                       float* __restrict__ out, int n) {
    int i = blockIdx.x * TPB + threadIdx.x;
    if (i >= n) return;

    // Scalar broadcast factors — issue first, overlap with x loads.
    float v_xn = f_xn[0], v_yn = f_yn[0], v_xp = f_xp[0], v_yp = f_yp[0];

    const float* p = x + (size_t)i * NFEAT;
    float sx   = __ldg(p + 0);
    float sy   = __ldg(p + 1);
    float tpx  = __ldg(p + 2);
    float tnx  = __ldg(p + 3);
    float tpy  = __ldg(p + 4);
    float tny  = __ldg(p + 5);
    float V    = __ldg(p + 6);
    float dist = __ldg(p + 7);

    float rd  = SUN_DIST * rcpf(dist);
    float irr = SOLAR_C * rd * rd;

    // Dark-side panel's root is negative -> clamps to 0; keep only lit side.
    bool  xp = sx > 0.0f;
    float Gx = irr * fabsf(sx);
    float Tx = xp ? tpx : tnx;
    float fx = xp ? v_xp : v_xn;

    bool  yp = sy > 0.0f;
    float Gy = irr * fabsf(sy);
    float Ty = yp ? tpy : tny;
    float fy = yp ? v_yp : v_yn;
    float cAY  = yp ? C_A2 : C_A1;     // y_pos: small cells, y_neg: large
    float parY = yp ? 10.0f : 6.0f;    // 180/18 vs 108/18

    float v_cell  = V * (1.0f / 18.0f);
    float inv_em1 = ex2f(INV_EM1_ARG);

    float gtx = (Gx * INV_GREF) * fmaf(ALPHA_ISC, Tx - T_REFC, 1.0f);
    float gty = (Gy * INV_GREF) * fmaf(ALPHA_ISC, Ty - T_REFC, 1.0f);

    float kx = (float)LOG2E * rcpf(NKB * Tx);
    float ky = (float)LOG2E * rcpf(NKB * Ty);

    float iph1 = C_A1 * gtx;           // X large cells  (parallel = 2)
    float iph2 = C_A2 * gtx;           // X small cells  (parallel = 7)
    float iph3 = cAY  * gty;           // Y selected config

    float i0_1 = C_A1 * inv_em1;
    float i0_2 = C_A2 * inv_em1;
    float i0_3 = cAY  * inv_em1;

    float c0_1 = iph1 + i0_1;
    float c0_2 = iph2 + i0_2;
    float c0_3 = iph3 + i0_3;

    float I1 = iph1, I2 = iph2, I3 = iph3;

    #pragma unroll
    for (int it = 0; it < NITER; ++it) {
        fp_step(I1, v_cell, c0_1, i0_1, kx);
        fp_step(I2, v_cell, c0_2, i0_2, kx);
        fp_step(I3, v_cell, c0_3, i0_3, ky);
    }

    float ix = fx * fmaf(2.0f, fmaxf(I1, 0.0f), 7.0f * fmaxf(I2, 0.0f));
    float iy = fy * parY * fmaxf(I3, 0.0f);
    out[i] = 0.92f * (ix + iy);
}

extern "C" void kernel_launch(void* const* d_in, const int* in_sizes, int n_in,
                              void* d_out, int out_size) {
    const float* x    = (const float*)d_in[0];
    const float* f_xn = (const float*)d_in[1];
    const float* f_yn = (const float*)d_in[2];
    const float* f_xp = (const float*)d_in[3];
    const float* f_yp = (const float*)d_in[4];
    float* out = (float*)d_out;

    int n = in_sizes[0] / NFEAT;
    int blocks = (n + TPB - 1) / TPB;
    segment_physics_kernel<<<blocks, TPB>>>(x, f_xn, f_yn, f_xp, f_yp, out, n);
}

// round 10
// speedup vs baseline: 1.0047x; 1.0047x over previous
#include <cuda_runtime.h>

// SegmentPhysicsModel — FINAL. Frozen at the session's best-measured
// configuration (R5; re-verified R9: rel_err bit-identical, wall within the
// established +-0.3us noise band; its two ncu samples 5.15/5.25us are the two
// lowest of the session).
//
// Why this is the stopping point: DRAM 14%, fma 6%, issue 25%, occ 38% —
// no SM resource is binding. Remaining time = kernel-launch/CTA-distribution
// overhead + one cold-DRAM latency ramp. Levers tested and measured <= noise:
// smem/warp staging, load widening, thread pairing (2/thread), grid geometry
// (128/256 TPB), chain shortening (1 vs 2 steps), occupancy (20% vs 40%).
//
// Algorithmic content vs reference:
//  * 6 Newton solves -> 3 sign-selected solves: X_POS/X_NEG share a config
//    and are mutually exclusive by sign(sun_x) (dark panel's root < 0,
//    clamped to 0); same for Y with per-sign config selection.
//  * 25 Newton iterations -> 2 damped division-free fixed-point steps:
//    in-range z = u/vt in [19.2, 31.1] makes the residual linear in I to
//    within ~3e-4, so each step contracts by <= ~3e-4; 2 steps reach the
//    same root to f32 precision (measured rel_err 1.2e-7 vs 1e-3 gate).
//  * exp via ex2.approx with log2e prefolded into 1/vt; all divides via
//    rcp.approx; expm1(Voc/vt_ref) folded to a compile-time ex2 constant.
//  * Only the 8 used features loaded (year/month/day never enter the math).

#define TPB        256
#define NFEAT      11

#define JSC        170.0
#define ALPHA_ISC  0.0006f
#define T_REFC     298.15f
#define RS         0.01f
#define INV_RSH    0.002f
#define INV_GREF   (1.0f/1366.0f)
#define SOLAR_C    1366.0f
#define SUN_DIST   149600000.0f
#define NKB        (2.5f * 8.617333262e-05f)
#define LOG2E      1.4426950408889634

#define VT_REF_D   (2.5 * 8.617333262e-05 * 298.15)
#define INV_EM1_ARG ((float)(-(2.35 / VT_REF_D) * LOG2E))

#define C_A1       ((float)(JSC * 0.0604 * 0.0398))
#define C_A2       ((float)(JSC * 0.0403 * 0.0306))

#define STEP       0.99984f
#define NITER      2

__device__ __forceinline__ float ex2f(float z) {
    float r;
    asm("ex2.approx.f32 %0, %1;" : "=f"(r) : "f"(z));
    return r;
}

__device__ __forceinline__ float rcpf(float a) {
    float r;
    asm("rcp.approx.f32 %0, %1;" : "=f"(r) : "f"(a));
    return r;
}

__device__ __forceinline__ void fp_step(float& I, float v_cell, float c0,
                                        float i0, float k) {
    float u = fmaf(I, RS, v_cell);
    float e = ex2f(u * k);
    float t = fmaf(-i0, e, c0);
    t = fmaf(-INV_RSH, u, t);
    I = fmaf(STEP, t - I, I);
}

__global__ void __launch_bounds__(TPB)
segment_physics_kernel(const float* __restrict__ x,
                       const float* __restrict__ f_xn,
                       const float* __restrict__ f_yn,
                       const float* __restrict__ f_xp,
                       const float* __restrict__ f_yp,
                       float* __restrict__ out, int n) {
    int i = blockIdx.x * TPB + threadIdx.x;
    if (i >= n) return;

    // Scalar broadcast factors — issue first, overlap with x loads.
    float v_xn = f_xn[0], v_yn = f_yn[0], v_xp = f_xp[0], v_yp = f_yp[0];

    const float* p = x + (size_t)i * NFEAT;
    float sx   = __ldg(p + 0);
    float sy   = __ldg(p + 1);
    float tpx  = __ldg(p + 2);
    float tnx  = __ldg(p + 3);
    float tpy  = __ldg(p + 4);
    float tny  = __ldg(p + 5);
    float V    = __ldg(p + 6);
    float dist = __ldg(p + 7);

    float rd  = SUN_DIST * rcpf(dist);
    float irr = SOLAR_C * rd * rd;

    // Dark-side panel's root is negative -> clamps to 0; keep only lit side.
    bool  xp = sx > 0.0f;
    float Gx = irr * fabsf(sx);
    float Tx = xp ? tpx : tnx;
    float fx = xp ? v_xp : v_xn;

    bool  yp = sy > 0.0f;
    float Gy = irr * fabsf(sy);
    float Ty = yp ? tpy : tny;
    float fy = yp ? v_yp : v_yn;
    float cAY  = yp ? C_A2 : C_A1;     // y_pos: small cells, y_neg: large
    float parY = yp ? 10.0f : 6.0f;    // 180/18 vs 108/18

    float v_cell  = V * (1.0f / 18.0f);
    float inv_em1 = ex2f(INV_EM1_ARG);

    float gtx = (Gx * INV_GREF) * fmaf(ALPHA_ISC, Tx - T_REFC, 1.0f);
    float gty = (Gy * INV_GREF) * fmaf(ALPHA_ISC, Ty - T_REFC, 1.0f);

    float kx = (float)LOG2E * rcpf(NKB * Tx);
    float ky = (float)LOG2E * rcpf(NKB * Ty);

    float iph1 = C_A1 * gtx;           // X large cells  (parallel = 2)
    float iph2 = C_A2 * gtx;           // X small cells  (parallel = 7)
    float iph3 = cAY  * gty;           // Y selected config

    float i0_1 = C_A1 * inv_em1;
    float i0_2 = C_A2 * inv_em1;
    float i0_3 = cAY  * inv_em1;

    float c0_1 = iph1 + i0_1;
    float c0_2 = iph2 + i0_2;
    float c0_3 = iph3 + i0_3;

    float I1 = iph1, I2 = iph2, I3 = iph3;

    #pragma unroll
    for (int it = 0; it < NITER; ++it) {
        fp_step(I1, v_cell, c0_1, i0_1, kx);
        fp_step(I2, v_cell, c0_2, i0_2, kx);
        fp_step(I3, v_cell, c0_3, i0_3, ky);
    }

    float ix = fx * fmaf(2.0f, fmaxf(I1, 0.0f), 7.0f * fmaxf(I2, 0.0f));
    float iy = fy * parY * fmaxf(I3, 0.0f);
    out[i] = 0.92f * (ix + iy);
}

extern "C" void kernel_launch(void* const* d_in, const int* in_sizes, int n_in,
                              void* d_out, int out_size) {
    const float* x    = (const float*)d_in[0];
    const float* f_xn = (const float*)d_in[1];
    const float* f_yn = (const float*)d_in[2];
    const float* f_xp = (const float*)d_in[3];
    const float* f_yp = (const float*)d_in[4];
    float* out = (float*)d_out;

    int n = in_sizes[0] / NFEAT;
    int blocks = (n + TPB - 1) / TPB;
    segment_physics_kernel<<<blocks, TPB>>>(x, f_xn, f_yn, f_xp, f_yp, out, n);
}